// round 9
// baseline (speedup 1.0000x reference)
#include <cuda_runtime.h>
#include <math.h>

#define NBITS   20
#define NSUB    ((1u << NBITS) - 1u)    // 1048575 elements in w
#define NT8     (1 << (NBITS - 3))      // 131072 threads, 8 elements each
#define NBLK    512
#define NTPB    256
#define NWARP   (NTPB / 32)
#define FULLM   0xFFFFFFFFu

// Per-block partial sums; fully overwritten by kernel A each launch.
__device__ float g_part[NBLK][NBITS + 1];

// ---------------- Kernel A: streaming bit-bin reduction ----------------
__global__ void __launch_bounds__(NTPB) mil_reduce_kernel(const float* __restrict__ w) {
    const int tid  = threadIdx.x;
    const int warp = tid >> 5;
    const int lane = tid & 31;
    const int t    = blockIdx.x * NTPB + tid;   // chunk id, 0..131071 (exact cover)
    const int e0   = t << 3;                    // first element index of this chunk

    // ---- load 8 elements v[0..7] (e = e0+k), 2 x LDG.128 ----
    float v[8];
    const float4* __restrict__ w4 = (const float4*)w;
    if (t != NT8 - 1) {
        float4 a = w4[(e0 >> 2) + 0];
        float4 b = w4[(e0 >> 2) + 1];
        v[0]=a.x; v[1]=a.y; v[2]=a.z; v[3]=a.w;
        v[4]=b.x; v[5]=b.y; v[6]=b.z; v[7]=b.w;
    } else {
        float4 a = w4[(e0 >> 2) + 0];
        v[0]=a.x; v[1]=a.y; v[2]=a.z; v[3]=a.w;
        v[4] = w[e0 + 4];
        v[5] = w[e0 + 5];
        v[6] = w[e0 + 6];
        v[7] = 0.0f;                    // i = 2^20 does not exist
    }

    // subset index of v[k] is i = 8t + (k+1).
    // v[0..6]: bits0-2 pattern = k+1, bits3-7 = lane, bits8-19 = cw   (t = 32*cw + lane)
    // v[7]:    i = 8(t+1): bits0-2 = 0; lanes 0..30: bits3-7 = lane+1, bits8+ = cw;
    //          lane 31:    bits3-7 = 0, bits8+ = cw+1.
    const float v7 = v[7];

    // bins 0..2 (bits 0-2 of i), per-thread
    float B0 = (v[0] + v[2]) + (v[4] + v[6]);
    float B1 = (v[1] + v[2]) + (v[5] + v[6]);
    float B2 = (v[3] + v[4]) + (v[5] + v[6]);
    const float S  = ((v[0] + v[1]) + (v[2] + v[3])) + ((v[4] + v[5]) + v[6]);

    // x_l: value whose bits3-7 pattern equals the lane id.
    float vs = __shfl_up_sync(FULLM, v7, 1);
    if (lane == 0) vs = 0.0f;
    float x = S + vs;
    const float v31 = __shfl_sync(FULLM, v7, 31);   // boundary element of the warp

    // ---- carry-accumulator butterfly: warp sum of x plus 5 lane-bit-masked sums ----
    float s = x, q;
    float A0, A1, A2, A3, A4;
    q = __shfl_xor_sync(FULLM, s, 1);  A0 = (lane & 1)  ? s : q;  s += q;
    q = __shfl_xor_sync(FULLM, s, 2);  A1 = (lane & 2)  ? s : q;  s += q;
    A0 += __shfl_xor_sync(FULLM, A0, 2);
    q = __shfl_xor_sync(FULLM, s, 4);  A2 = (lane & 4)  ? s : q;  s += q;
    A0 += __shfl_xor_sync(FULLM, A0, 4);
    A1 += __shfl_xor_sync(FULLM, A1, 4);
    q = __shfl_xor_sync(FULLM, s, 8);  A3 = (lane & 8)  ? s : q;  s += q;
    A0 += __shfl_xor_sync(FULLM, A0, 8);
    A1 += __shfl_xor_sync(FULLM, A1, 8);
    A2 += __shfl_xor_sync(FULLM, A2, 8);
    q = __shfl_xor_sync(FULLM, s, 16); A4 = (lane & 16) ? s : q;  s += q;
    A0 += __shfl_xor_sync(FULLM, A0, 16);
    A1 += __shfl_xor_sync(FULLM, A1, 16);
    A2 += __shfl_xor_sync(FULLM, A2, 16);
    A3 += __shfl_xor_sync(FULLM, A3, 16);
    const float W = s;        // = sum of the 32 bits3-7-indexed values of this warp

    // plain butterflies for bins 0..2
#pragma unroll
    for (int o = 16; o > 0; o >>= 1) B0 += __shfl_xor_sync(FULLM, B0, o);
#pragma unroll
    for (int o = 16; o > 0; o >>= 1) B1 += __shfl_xor_sync(FULLM, B1, o);
#pragma unroll
    for (int o = 16; o > 0; o >>= 1) B2 += __shfl_xor_sync(FULLM, B2, o);

    // ---- per-warp 21-vector; lane l computes bin l ----
    const unsigned cw  = (unsigned)(blockIdx.x * NWARP + warp);   // bits 8-19 of i for in-warp elems
    const unsigned cw1 = cw + 1u;                                  // ... for the warp-boundary elem
    __shared__ float sw[NWARP][NBITS + 1];
    if (lane <= NBITS) {
        float val;
        if      (lane == 0) val = B0;
        else if (lane == 1) val = B1;
        else if (lane == 2) val = B2;
        else if (lane == 3) val = A0;
        else if (lane == 4) val = A1;
        else if (lane == 5) val = A2;
        else if (lane == 6) val = A3;
        else if (lane == 7) val = A4;
        else if (lane < NBITS) {
            const int bb = lane - 8;                   // bit bb of cw / cw1
            val = ((cw  >> bb) & 1u ? W   : 0.0f)
                + ((cw1 >> bb) & 1u ? v31 : 0.0f);
        } else {
            val = W + v31;                              // bin 20: total sum
        }
        sw[warp][lane] = val;
    }
    __syncthreads();

    if (tid <= NBITS) {
        float a = sw[0][tid];
#pragma unroll
        for (int ww = 1; ww < NWARP; ww++) a += sw[ww][tid];
        g_part[blockIdx.x][tid] = a;
    }
}

// ---------------- Kernel B: parallel finalize ----------------
__global__ void __launch_bounds__(NTPB) mil_finalize_kernel(const float* __restrict__ yprob,
                                                            const int*   __restrict__ Yp,
                                                            int has_Y,
                                                            float* __restrict__ out) {
    const int tid  = threadIdx.x;
    const int warp = tid >> 5;
    const int lane = tid & 31;

    // Parallel gather: thread tid sums rows tid and tid+256 (42 independent L2 loads).
    float r[NBITS + 1];
#pragma unroll
    for (int b = 0; b <= NBITS; b++)
        r[b] = g_part[tid][b] + g_part[tid + NTPB][b];

    // warp butterfly each bin
#pragma unroll
    for (int b = 0; b <= NBITS; b++) {
        float z = r[b];
#pragma unroll
        for (int o = 16; o > 0; o >>= 1) z += __shfl_xor_sync(FULLM, z, o);
        r[b] = z;
    }

    __shared__ float sw[NWARP][NBITS + 1];
    __shared__ float lp[NBITS], l1[NBITS], sfin[NBITS + 1];
    if (lane == 0) {
#pragma unroll
        for (int b = 0; b <= NBITS; b++) sw[warp][b] = r[b];
    }

    // fp32 logs in parallel (matches reference fp32 log)
    if (tid < NBITS) {
        float pp = yprob[tid];
        lp[tid] = logf(pp);
        l1[tid] = logf(1.0f - pp);
    }
    __syncthreads();

    if (tid <= NBITS) {
        float a = sw[0][tid];
#pragma unroll
        for (int ww = 1; ww < NWARP; ww++) a += sw[ww][tid];
        sfin[tid] = a;
    }
    __syncthreads();

    if (tid == 0) {
        int y_nonzero = 1;
        if (has_Y) y_nonzero = (Yp[0] != 0);

        double basee = 0.0;
#pragma unroll
        for (int j = 0; j < NBITS; j++) basee += (double)l1[j];

        if (y_nonzero) {
            double res = basee * (double)sfin[NBITS];
#pragma unroll
            for (int b = 0; b < NBITS; b++) {
                int j = NBITS - 1 - b;     // column j <-> bit (NBITS-1-j) of subset index
                res += ((double)lp[j] - (double)l1[j]) * (double)sfin[b];
            }
            out[0] = (float)res;
        } else {
            out[0] = (float)((double)NSUB * basee);
        }
    }
}

extern "C" void kernel_launch(void* const* d_in, const int* in_sizes, int n_in,
                              void* d_out, int out_size) {
    const float* yprob = (const float*)d_in[0];
    const float* w     = (const float*)d_in[1];
    const int*   Yp    = (n_in >= 3) ? (const int*)d_in[2] : nullptr;
    float*       out   = (float*)d_out;
    (void)in_sizes; (void)out_size;

    mil_reduce_kernel<<<NBLK, NTPB>>>(w);
    mil_finalize_kernel<<<1, NTPB>>>(yprob, Yp, Yp != nullptr ? 1 : 0, out);
}

// round 10
// speedup vs baseline: 1.4090x; 1.4090x over previous
#include <cuda_runtime.h>
#include <math.h>

#define NBITS   20
#define NSUB    ((1u << NBITS) - 1u)    // 1048575 elements in w
#define NT8     (1 << (NBITS - 3))      // 131072 threads, 8 elements each
#define NBLK    512
#define NTPB    256
#define NWARP   (NTPB / 32)
#define FULLM   0xFFFFFFFFu

// Coefficient vector (padded to 32 lanes; lanes 21..31 = 0). Written by the
// pre-kernel every launch -> replay-safe, no persistent state.
__device__ float g_coeff[32];

// ---------------- Pre-kernel: coefficients + output init ----------------
// coeff[b]  (b<20) = logp[19-b] - log1mp[19-b]   (bin b counts bit b of subset idx)
// coeff[20]        = sum_j log1mp[j]             (multiplies the total-sum bin)
// Y==1: out[0] = 0 (accumulated by main kernel). Y==0: out[0] = NSUB * base, coeff = 0.
__global__ void mil_pre_kernel(const float* __restrict__ yprob,
                               const int*   __restrict__ Yp,
                               int has_Y,
                               float* __restrict__ out) {
    const int t = threadIdx.x;

    __shared__ float lp[NBITS], l1[NBITS];
    if (t < NBITS) {
        float pp = yprob[t];
        lp[t] = logf(pp);
        l1[t] = logf(1.0f - pp);
    }
    __syncwarp();

    int y_nonzero = 1;
    if (has_Y) y_nonzero = (Yp[0] != 0);

    // base = sum of l1 (serial in double by lane 0 -- 20 adds, trivial)
    if (t == 0) {
        double basee = 0.0;
#pragma unroll
        for (int j = 0; j < NBITS; j++) basee += (double)l1[j];
        if (y_nonzero) {
            g_coeff[NBITS] = (float)basee;
            out[0] = 0.0f;
        } else {
            g_coeff[NBITS] = 0.0f;
            out[0] = (float)((double)NSUB * basee);
        }
    }
    if (t < NBITS)
        g_coeff[t] = y_nonzero ? (lp[NBITS - 1 - t] - l1[NBITS - 1 - t]) : 0.0f;
    if (t > NBITS)
        g_coeff[t] = 0.0f;
}

// ---------------- Main kernel: bin + dot + single atomic per block ----------------
__global__ void __launch_bounds__(NTPB) mil_main_kernel(const float* __restrict__ w,
                                                        float* __restrict__ out) {
    const int tid  = threadIdx.x;
    const int warp = tid >> 5;
    const int lane = tid & 31;
    const int t    = blockIdx.x * NTPB + tid;   // chunk id, 0..131071 (exact cover)
    const int e0   = t << 3;                    // first element index of this chunk

    // ---- load 8 elements v[0..7] (e = e0+k), 2 x LDG.128 ----
    float v[8];
    const float4* __restrict__ w4 = (const float4*)w;
    if (t != NT8 - 1) {
        float4 a = w4[(e0 >> 2) + 0];
        float4 b = w4[(e0 >> 2) + 1];
        v[0]=a.x; v[1]=a.y; v[2]=a.z; v[3]=a.w;
        v[4]=b.x; v[5]=b.y; v[6]=b.z; v[7]=b.w;
    } else {
        float4 a = w4[(e0 >> 2) + 0];
        v[0]=a.x; v[1]=a.y; v[2]=a.z; v[3]=a.w;
        v[4] = w[e0 + 4];
        v[5] = w[e0 + 5];
        v[6] = w[e0 + 6];
        v[7] = 0.0f;                    // i = 2^20 does not exist
    }

    // subset index of v[k] is i = 8t + (k+1).
    // v[0..6]: bits0-2 pattern = k+1, bits3-7 = lane, bits8-19 = cw   (t = 32*cw + lane)
    // v[7]:    i = 8(t+1): lanes 0..30: bits3-7 = lane+1, bits8+ = cw;
    //          lane 31:    bits3-7 = 0, bits8+ = cw+1.
    const float v7 = v[7];

    // bins 0..2 (bits 0-2 of i), per-thread
    float B0 = (v[0] + v[2]) + (v[4] + v[6]);
    float B1 = (v[1] + v[2]) + (v[5] + v[6]);
    float B2 = (v[3] + v[4]) + (v[5] + v[6]);
    const float S  = ((v[0] + v[1]) + (v[2] + v[3])) + ((v[4] + v[5]) + v[6]);

    // x_l: value whose bits3-7 pattern equals the lane id.
    float vs = __shfl_up_sync(FULLM, v7, 1);
    if (lane == 0) vs = 0.0f;
    float x = S + vs;
    const float v31 = __shfl_sync(FULLM, v7, 31);   // boundary element of the warp

    // ---- carry-accumulator butterfly: warp sum of x plus 5 lane-bit-masked sums ----
    float s = x, q;
    float A0, A1, A2, A3, A4;
    q = __shfl_xor_sync(FULLM, s, 1);  A0 = (lane & 1)  ? s : q;  s += q;
    q = __shfl_xor_sync(FULLM, s, 2);  A1 = (lane & 2)  ? s : q;  s += q;
    A0 += __shfl_xor_sync(FULLM, A0, 2);
    q = __shfl_xor_sync(FULLM, s, 4);  A2 = (lane & 4)  ? s : q;  s += q;
    A0 += __shfl_xor_sync(FULLM, A0, 4);
    A1 += __shfl_xor_sync(FULLM, A1, 4);
    q = __shfl_xor_sync(FULLM, s, 8);  A3 = (lane & 8)  ? s : q;  s += q;
    A0 += __shfl_xor_sync(FULLM, A0, 8);
    A1 += __shfl_xor_sync(FULLM, A1, 8);
    A2 += __shfl_xor_sync(FULLM, A2, 8);
    q = __shfl_xor_sync(FULLM, s, 16); A4 = (lane & 16) ? s : q;  s += q;
    A0 += __shfl_xor_sync(FULLM, A0, 16);
    A1 += __shfl_xor_sync(FULLM, A1, 16);
    A2 += __shfl_xor_sync(FULLM, A2, 16);
    A3 += __shfl_xor_sync(FULLM, A3, 16);
    const float W = s;        // = sum of the 32 bits3-7-indexed values of this warp

    // plain butterflies for bins 0..2
#pragma unroll
    for (int o = 16; o > 0; o >>= 1) B0 += __shfl_xor_sync(FULLM, B0, o);
#pragma unroll
    for (int o = 16; o > 0; o >>= 1) B1 += __shfl_xor_sync(FULLM, B1, o);
#pragma unroll
    for (int o = 16; o > 0; o >>= 1) B2 += __shfl_xor_sync(FULLM, B2, o);

    // ---- per-warp bin value on lane l, times coefficient, then dot via butterfly ----
    const unsigned cw  = (unsigned)(blockIdx.x * NWARP + warp);   // bits 8-19 of i
    const unsigned cw1 = cw + 1u;
    float val = 0.0f;
    if (lane <= NBITS) {
        if      (lane == 0) val = B0;
        else if (lane == 1) val = B1;
        else if (lane == 2) val = B2;
        else if (lane == 3) val = A0;
        else if (lane == 4) val = A1;
        else if (lane == 5) val = A2;
        else if (lane == 6) val = A3;
        else if (lane == 7) val = A4;
        else if (lane < NBITS) {
            const int bb = lane - 8;
            val = ((cw  >> bb) & 1u ? W   : 0.0f)
                + ((cw1 >> bb) & 1u ? v31 : 0.0f);
        } else {
            val = W + v31;                          // bin 20: total sum
        }
    }
    val *= g_coeff[lane];                           // lanes >20 read 0

    // dot-product reduce across the warp
#pragma unroll
    for (int o = 16; o > 0; o >>= 1) val += __shfl_xor_sync(FULLM, val, o);

    // ---- block fold: 8 warp scalars -> one atomicAdd ----
    __shared__ float sp[NWARP];
    if (lane == 0) sp[warp] = val;
    __syncthreads();
    if (tid == 0) {
        float a = ((sp[0] + sp[1]) + (sp[2] + sp[3]))
                + ((sp[4] + sp[5]) + (sp[6] + sp[7]));
        atomicAdd(out, a);
    }
}

extern "C" void kernel_launch(void* const* d_in, const int* in_sizes, int n_in,
                              void* d_out, int out_size) {
    const float* yprob = (const float*)d_in[0];
    const float* w     = (const float*)d_in[1];
    const int*   Yp    = (n_in >= 3) ? (const int*)d_in[2] : nullptr;
    float*       out   = (float*)d_out;
    (void)in_sizes; (void)out_size;

    mil_pre_kernel<<<1, 32>>>(yprob, Yp, Yp != nullptr ? 1 : 0, out);
    mil_main_kernel<<<NBLK, NTPB>>>(w, out);
}

// round 11
// speedup vs baseline: 1.8366x; 1.3035x over previous
#include <cuda_runtime.h>
#include <math.h>

#define NBITS   20
#define NSUB    ((1u << NBITS) - 1u)    // 1048575 elements in w
#define NT8     (1 << (NBITS - 3))      // 131072 threads, 8 elements each
#define NBLK    512
#define NTPB    256
#define NWARP   (NTPB / 32)
#define FULLM   0xFFFFFFFFu

// Single kernel: per-warp coefficient computation (overlapped with w-load
// latency), bit-bin warp reduction, in-warp dot product, one atomicAdd per
// block into the memset-zeroed output.
__global__ void __launch_bounds__(NTPB) mil_main_kernel(const float* __restrict__ w,
                                                        const float* __restrict__ yprob,
                                                        const int*   __restrict__ Yp,
                                                        int has_Y,
                                                        float* __restrict__ out) {
    const int tid  = threadIdx.x;
    const int warp = tid >> 5;
    const int lane = tid & 31;
    const int t    = blockIdx.x * NTPB + tid;   // chunk id, 0..131071 (exact cover)
    const int e0   = t << 3;                    // first element index of this chunk

    // ---- issue the 8-element load FIRST (2 x LDG.128) so its latency hides
    //      the coefficient math below ----
    float v[8];
    const float4* __restrict__ w4 = (const float4*)w;
    if (t != NT8 - 1) {
        float4 a = w4[(e0 >> 2) + 0];
        float4 b = w4[(e0 >> 2) + 1];
        v[0]=a.x; v[1]=a.y; v[2]=a.z; v[3]=a.w;
        v[4]=b.x; v[5]=b.y; v[6]=b.z; v[7]=b.w;
    } else {
        float4 a = w4[(e0 >> 2) + 0];
        v[0]=a.x; v[1]=a.y; v[2]=a.z; v[3]=a.w;
        v[4] = w[e0 + 4];
        v[5] = w[e0 + 5];
        v[6] = w[e0 + 6];
        v[7] = 0.0f;                    // i = 2^20 does not exist
    }

    // ---- per-warp coefficient vector (independent of the loads) ----
    // coeff[b] (b<20) = logp[19-b] - log1mp[19-b]; coeff[20] = sum_j log1mp[j];
    // lanes 21..31 -> 0. Y==0 -> all coeffs 0 (block 0 adds the closed form).
    const int   y_nonzero = has_Y ? (Yp[0] != 0) : 1;
    const float pp   = (lane < NBITS) ? yprob[lane] : 0.5f;   // dummy for pad lanes
    const float lpv  = logf(pp);
    const float l1v  = logf(1.0f - pp);
    const float diff = lpv - l1v;
    float base = (lane < NBITS) ? l1v : 0.0f;                 // -> sum of log1mp
#pragma unroll
    for (int o = 16; o > 0; o >>= 1) base += __shfl_xor_sync(FULLM, base, o);
    const int   src   = (lane < NBITS) ? (NBITS - 1 - lane) : 0;
    const float cdiff = __shfl_sync(FULLM, diff, src);
    float coeff;
    if      (lane <  NBITS) coeff = cdiff;
    else if (lane == NBITS) coeff = base;
    else                    coeff = 0.0f;
    if (!y_nonzero)         coeff = 0.0f;

    // subset index of v[k] is i = 8t + (k+1).
    // v[0..6]: bits0-2 pattern = k+1, bits3-7 = lane, bits8-19 = cw   (t = 32*cw + lane)
    // v[7]:    i = 8(t+1): lanes 0..30: bits3-7 = lane+1, bits8+ = cw;
    //          lane 31:    bits3-7 = 0, bits8+ = cw+1.
    const float v7 = v[7];

    // bins 0..2 (bits 0-2 of i), per-thread
    float B0 = (v[0] + v[2]) + (v[4] + v[6]);
    float B1 = (v[1] + v[2]) + (v[5] + v[6]);
    float B2 = (v[3] + v[4]) + (v[5] + v[6]);
    const float S  = ((v[0] + v[1]) + (v[2] + v[3])) + ((v[4] + v[5]) + v[6]);

    // x_l: value whose bits3-7 pattern equals the lane id.
    float vs = __shfl_up_sync(FULLM, v7, 1);
    if (lane == 0) vs = 0.0f;
    float x = S + vs;
    const float v31 = __shfl_sync(FULLM, v7, 31);   // boundary element of the warp

    // ---- carry-accumulator butterfly: warp sum of x plus 5 lane-bit-masked sums ----
    float s = x, q;
    float A0, A1, A2, A3, A4;
    q = __shfl_xor_sync(FULLM, s, 1);  A0 = (lane & 1)  ? s : q;  s += q;
    q = __shfl_xor_sync(FULLM, s, 2);  A1 = (lane & 2)  ? s : q;  s += q;
    A0 += __shfl_xor_sync(FULLM, A0, 2);
    q = __shfl_xor_sync(FULLM, s, 4);  A2 = (lane & 4)  ? s : q;  s += q;
    A0 += __shfl_xor_sync(FULLM, A0, 4);
    A1 += __shfl_xor_sync(FULLM, A1, 4);
    q = __shfl_xor_sync(FULLM, s, 8);  A3 = (lane & 8)  ? s : q;  s += q;
    A0 += __shfl_xor_sync(FULLM, A0, 8);
    A1 += __shfl_xor_sync(FULLM, A1, 8);
    A2 += __shfl_xor_sync(FULLM, A2, 8);
    q = __shfl_xor_sync(FULLM, s, 16); A4 = (lane & 16) ? s : q;  s += q;
    A0 += __shfl_xor_sync(FULLM, A0, 16);
    A1 += __shfl_xor_sync(FULLM, A1, 16);
    A2 += __shfl_xor_sync(FULLM, A2, 16);
    A3 += __shfl_xor_sync(FULLM, A3, 16);
    const float W = s;        // = sum of the 32 bits3-7-indexed values of this warp

    // plain butterflies for bins 0..2
#pragma unroll
    for (int o = 16; o > 0; o >>= 1) B0 += __shfl_xor_sync(FULLM, B0, o);
#pragma unroll
    for (int o = 16; o > 0; o >>= 1) B1 += __shfl_xor_sync(FULLM, B1, o);
#pragma unroll
    for (int o = 16; o > 0; o >>= 1) B2 += __shfl_xor_sync(FULLM, B2, o);

    // ---- per-warp bin value on lane l, times coefficient, then dot via butterfly ----
    const unsigned cw  = (unsigned)(blockIdx.x * NWARP + warp);   // bits 8-19 of i
    const unsigned cw1 = cw + 1u;
    float val = 0.0f;
    if (lane <= NBITS) {
        if      (lane == 0) val = B0;
        else if (lane == 1) val = B1;
        else if (lane == 2) val = B2;
        else if (lane == 3) val = A0;
        else if (lane == 4) val = A1;
        else if (lane == 5) val = A2;
        else if (lane == 6) val = A3;
        else if (lane == 7) val = A4;
        else if (lane < NBITS) {
            const int bb = lane - 8;
            val = ((cw  >> bb) & 1u ? W   : 0.0f)
                + ((cw1 >> bb) & 1u ? v31 : 0.0f);
        } else {
            val = W + v31;                          // bin 20: total sum
        }
    }
    val *= coeff;                                   // lanes >20 have coeff 0

    // dot-product reduce across the warp
#pragma unroll
    for (int o = 16; o > 0; o >>= 1) val += __shfl_xor_sync(FULLM, val, o);

    // ---- block fold: 8 warp scalars -> one atomicAdd ----
    __shared__ float sp[NWARP];
    if (lane == 0) sp[warp] = val;
    __syncthreads();
    if (tid == 0) {
        float a = ((sp[0] + sp[1]) + (sp[2] + sp[3]))
                + ((sp[4] + sp[5]) + (sp[6] + sp[7]));
        // Y==0 closed form: all coeffs were 0 (every block adds 0); block 0
        // adds the full result NSUB * sum(log1mp).
        if (!y_nonzero && blockIdx.x == 0)
            a += (float)((double)NSUB * (double)base);
        atomicAdd(out, a);
    }
}

extern "C" void kernel_launch(void* const* d_in, const int* in_sizes, int n_in,
                              void* d_out, int out_size) {
    const float* yprob = (const float*)d_in[0];
    const float* w     = (const float*)d_in[1];
    const int*   Yp    = (n_in >= 3) ? (const int*)d_in[2] : nullptr;
    float*       out   = (float*)d_out;
    (void)in_sizes; (void)out_size;

    cudaMemsetAsync(out, 0, sizeof(float));   // graph-capturable memset node
    mil_main_kernel<<<NBLK, NTPB>>>(w, yprob, Yp, Yp != nullptr ? 1 : 0, out);
}

// round 12
// speedup vs baseline: 1.8583x; 1.0118x over previous
#include <cuda_runtime.h>
#include <math.h>

#define NBITS   20
#define NSUB    ((1u << NBITS) - 1u)    // 1048575 elements in w
#define NT16    (1 << (NBITS - 4))      // 65536 threads, 16 elements each
#define NBLK    512
#define NTPB    128
#define NWARP   (NTPB / 32)
#define FULLM   0xFFFFFFFFu

// Single pass: per-element dot with the per-subset coefficient, decomposed as
// c_i = c_low4(i & 15) + c_high(i >> 4). Coefficients built in smem by warp 0
// while every thread's 4 LDG.128 are in flight.
__global__ void __launch_bounds__(NTPB) mil_main_kernel(const float* __restrict__ w,
                                                        const float* __restrict__ yprob,
                                                        const int*   __restrict__ Yp,
                                                        int has_Y,
                                                        float* __restrict__ out) {
    const int tid  = threadIdx.x;
    const int warp = tid >> 5;
    const int lane = tid & 31;
    const int t    = blockIdx.x * NTPB + tid;   // chunk id, 0..65535 (exact cover)
    const int e0   = t << 4;                    // first element index of this chunk

    // ---- issue all 4 LDG.128 first; latency hides the coefficient setup ----
    float v[16];
    const float4* __restrict__ w4 = (const float4*)w;
    if (t != NT16 - 1) {
#pragma unroll
        for (int g = 0; g < 4; g++) {
            float4 a = w4[(e0 >> 2) + g];
            v[4*g+0]=a.x; v[4*g+1]=a.y; v[4*g+2]=a.z; v[4*g+3]=a.w;
        }
    } else {
#pragma unroll
        for (int g = 0; g < 3; g++) {
            float4 a = w4[(e0 >> 2) + g];
            v[4*g+0]=a.x; v[4*g+1]=a.y; v[4*g+2]=a.z; v[4*g+3]=a.w;
        }
        v[12] = w[e0 + 12];
        v[13] = w[e0 + 13];
        v[14] = w[e0 + 14];
        v[15] = 0.0f;                    // subset index 2^20 does not exist
    }

    // ---- warp 0 builds cf[0..20] and the low-4-bit table cl4[16] in smem ----
    // cf[b] (b<20) = coefficient of bit b of the subset index = logp[19-b]-log1mp[19-b]
    // cf[20]       = sum_j log1mp[j]  (constant term of every c_i)
    __shared__ float cf[NBITS + 1];
    __shared__ float cl4[16];
    __shared__ float sp[NWARP];
    const int y_nonzero = has_Y ? (Yp[0] != 0) : 1;
    float base = 0.0f;                           // valid on warp 0 after reduce
    if (warp == 0) {
        const float pp  = (lane < NBITS) ? yprob[lane] : 0.5f;
        const float lpv = logf(pp);
        const float l1v = logf(1.0f - pp);
        const float diff = lpv - l1v;
        float b1 = (lane < NBITS) ? l1v : 0.0f;
#pragma unroll
        for (int o = 16; o > 0; o >>= 1) b1 += __shfl_xor_sync(FULLM, b1, o);
        base = b1;                               // sum of log1mp
        const int   src   = (lane < NBITS) ? (NBITS - 1 - lane) : 0;
        const float cdiff = __shfl_sync(FULLM, diff, src);
        float cv;
        if      (lane <  NBITS) cv = cdiff;
        else if (lane == NBITS) cv = base;
        else                    cv = 0.0f;
        if (!y_nonzero)         cv = 0.0f;       // Y==0: closed form added by block 0
        if (lane <= NBITS) cf[lane] = cv;

        const float c0 = __shfl_sync(FULLM, cv, 0);
        const float c1 = __shfl_sync(FULLM, cv, 1);
        const float c2 = __shfl_sync(FULLM, cv, 2);
        const float c3 = __shfl_sync(FULLM, cv, 3);
        if (lane < 16) {
            float s = 0.0f;
            if (lane & 1) s += c0;
            if (lane & 2) s += c1;
            if (lane & 4) s += c2;
            if (lane & 8) s += c3;
            cl4[lane] = s;
        }
    }
    __syncthreads();

    // ---- c_high for this chunk (bits >=4 of i equal bits of t) and for the
    //      boundary element (bits of t+1). t < 2^16, so 16 bits suffice;
    //      t+1 == 2^16 only when v[15] == 0, so dropping bit 16 is harmless. ----
    const unsigned ut  = (unsigned)t;
    const unsigned ut1 = ut + 1u;
    float ch  = cf[NBITS];
    float ch2 = cf[NBITS];
#pragma unroll
    for (int b = 0; b < 16; b++) {
        const float c = cf[4 + b];
        if ((ut  >> b) & 1u) ch  += c;
        if ((ut1 >> b) & 1u) ch2 += c;
    }

    // ---- per-element dot: elements k=0..14 have low4 = k+1; element 15 has low4=0 ----
    float a0 = 0.0f, a1 = 0.0f, a2 = 0.0f, a3 = 0.0f;
#pragma unroll
    for (int k = 0; k < 12; k += 4) {
        a0 = fmaf(v[k+0], cl4[k+1], a0);
        a1 = fmaf(v[k+1], cl4[k+2], a1);
        a2 = fmaf(v[k+2], cl4[k+3], a2);
        a3 = fmaf(v[k+3], cl4[k+4], a3);
    }
    a0 = fmaf(v[12], cl4[13], a0);
    a1 = fmaf(v[13], cl4[14], a1);
    a2 = fmaf(v[14], cl4[15], a2);

    // S15 = sum of v[0..14], clean pairwise tree (no shared subterms)
    const float s01 = v[0] + v[1],  s23 = v[2] + v[3];
    const float s45 = v[4] + v[5],  s67 = v[6] + v[7];
    const float s89 = v[8] + v[9],  sAB = v[10] + v[11];
    const float sCD = v[12] + v[13];
    const float S15 = ((s01 + s23) + (s45 + s67)) + ((s89 + sAB) + (sCD + v[14]));

    float acc = ((a0 + a1) + (a2 + a3)) + ch * S15 + ch2 * v[15];

    // ---- warp reduce, block fold, one atomic per block ----
#pragma unroll
    for (int o = 16; o > 0; o >>= 1) acc += __shfl_xor_sync(FULLM, acc, o);
    if (lane == 0) sp[warp] = acc;
    __syncthreads();
    if (tid == 0) {
        float a = (sp[0] + sp[1]) + (sp[2] + sp[3]);
        if (!y_nonzero && blockIdx.x == 0)
            a += (float)((double)NSUB * (double)base);
        atomicAdd(out, a);
    }
}

extern "C" void kernel_launch(void* const* d_in, const int* in_sizes, int n_in,
                              void* d_out, int out_size) {
    const float* yprob = (const float*)d_in[0];
    const float* w     = (const float*)d_in[1];
    const int*   Yp    = (n_in >= 3) ? (const int*)d_in[2] : nullptr;
    float*       out   = (float*)d_out;
    (void)in_sizes; (void)out_size;

    cudaMemsetAsync(out, 0, sizeof(float));   // graph-capturable memset node
    mil_main_kernel<<<NBLK, NTPB>>>(w, yprob, Yp, Yp != nullptr ? 1 : 0, out);
}